// round 5
// baseline (speedup 1.0000x reference)
#include <cuda_runtime.h>
#include <string.h>

#define Bdim 512
#define Ldim 512
#define Tdim 128
#define START_TAG 126
#define STOP_TAG 127
#define NEGV (-10000.0f)
#define LOG2E 1.4426950408889634f
#define LN2   0.6931471805599453f
#define PF 8              // emission prefetch depth / unroll factor
#define NWORK 152         // persistent CTAs (1 per SM)
#define NJOBS (Bdim / 2)  // pair jobs

__device__ float g_partial[Bdim];     // per-batch forward - gold
__device__ int   g_counter;           // work queue head
__device__ int   g_done;              // completion counter
__device__ int   g_order[Bdim];       // batch ids sorted by len desc

__device__ __forceinline__ void fma2(unsigned long long& d,
                                     unsigned long long a,
                                     unsigned long long b) {
    asm("fma.rn.f32x2 %0, %1, %2, %0;" : "+l"(d) : "l"(a), "l"(b));
}
__device__ __forceinline__ float rcp_fast(float x) {
    float r;
    asm("rcp.approx.f32 %0, %1;" : "=f"(r) : "f"(x));
    return r;
}

// s[t] = sum_p et[t,p] * gs[p], et packed f32x2 in registers
__device__ __forceinline__ float matvec128(const float* gs,
                                           const unsigned long long* et) {
    const ulonglong2* g2 = reinterpret_cast<const ulonglong2*>(gs);
    unsigned long long a0 = 0, a1 = 0, a2 = 0, a3 = 0;
    #pragma unroll
    for (int k = 0; k < 32; k += 2) {
        ulonglong2 u = g2[k];
        ulonglong2 v = g2[k + 1];
        fma2(a0, et[2 * k + 0], u.x);
        fma2(a1, et[2 * k + 1], u.y);
        fma2(a2, et[2 * k + 2], v.x);
        fma2(a3, et[2 * k + 3], v.y);
    }
    float2 f0, f1, f2, f3;
    memcpy(&f0, &a0, 8); memcpy(&f1, &a1, 8);
    memcpy(&f2, &a2, 8); memcpy(&f3, &a3, 8);
    return ((f0.x + f0.y) + (f1.x + f1.y)) + ((f2.x + f2.y) + (f3.x + f3.y));
}

// terminal LSE + gold score; returns forward_score - gold_score (all threads)
__device__ __forceinline__ float finish_batch(
    float fv, int len, int b, int t, int lane, int warp,
    const float* __restrict__ feats, const float* __restrict__ trans,
    const int* __restrict__ tags, float* smax, float* ssum)
{
    float term = fv + trans[START_TAG * Tdim + t];
    float m2 = term;
    #pragma unroll
    for (int o = 16; o > 0; o >>= 1)
        m2 = fmaxf(m2, __shfl_xor_sync(0xffffffffu, m2, o));
    if (lane == 0) smax[warp] = m2;
    __syncthreads();
    m2 = fmaxf(fmaxf(smax[0], smax[1]), fmaxf(smax[2], smax[3]));

    float ex = exp2f((term - m2) * LOG2E);
    #pragma unroll
    for (int o = 16; o > 0; o >>= 1)
        ex += __shfl_xor_sync(0xffffffffu, ex, o);
    if (lane == 0) ssum[warp] = ex;
    __syncthreads();
    float fwd = m2 + __logf((ssum[0] + ssum[1]) + (ssum[2] + ssum[3]));
    __syncthreads();

    float acc = 0.f;
    const int* tg = tags + b * Ldim;
    for (int j = t; j <= len; j += Tdim) {
        int pa, pb;
        if (j == 0)        { pa = START_TAG;   pb = tg[0];    }
        else if (j == len) { pa = tg[len - 1]; pb = STOP_TAG; }
        else               { pa = tg[j - 1];   pb = tg[j];    }
        acc += trans[pb * Tdim + pa];
    }
    for (int i = t; i < len; i += Tdim) {
        int tag = tg[i];
        acc += feats[((size_t)b * Ldim + i) * Tdim + tag];
    }
    #pragma unroll
    for (int o = 16; o > 0; o >>= 1)
        acc += __shfl_xor_sync(0xffffffffu, acc, o);
    if (lane == 0) ssum[warp] = acc;
    __syncthreads();
    float gold = (ssum[0] + ssum[1]) + (ssum[2] + ssum[3]);
    __syncthreads();
    return fwd - gold;
}

// rank batches by length (desc, stable) + reset counters. grid 8 x 64
__global__ __launch_bounds__(64) void crf_schedule_kernel(const int* __restrict__ lens)
{
    __shared__ int sl[Bdim];
    const int tb = threadIdx.x;
    for (int k = tb; k < Bdim; k += 64) sl[k] = lens[k];
    __syncthreads();
    const int me = blockIdx.x * 64 + tb;
    const int myl = sl[me];
    int rank = 0;
    #pragma unroll 8
    for (int j = 0; j < Bdim; j++) {
        int lj = sl[j];
        rank += (lj > myl) || (lj == myl && j < me);
    }
    g_order[rank] = me;
    if (me == 0) { g_counter = NWORK; g_done = 0; }
}

__global__ __launch_bounds__(Tdim) void crf_batch_kernel(
    const float* __restrict__ feats,        // [B, L, T]
    const float* __restrict__ trans,        // [T, T]  trans[next, prev]
    const int*   __restrict__ tags,         // [B, L]
    const int*   __restrict__ lens,         // [B]
    float*       __restrict__ out)
{
    const int t    = threadIdx.x;           // this thread owns state 't'
    const int lane = t & 31;
    const int warp = t >> 5;

    __shared__ __align__(16) float gs1[2][Tdim];
    __shared__ __align__(16) float gs2[2][Tdim];
    __shared__ float sh_w1[2], sh_w2[2];
    __shared__ float smax[4];
    __shared__ float ssum[4];
    __shared__ int   sh_job;
    __shared__ int   sh_last;

    // ---- precompute exp(trans[t, :]) packed f32x2 into registers ----
    unsigned long long et[Tdim / 2];
    {
        const float4* trow = reinterpret_cast<const float4*>(trans + t * Tdim);
        #pragma unroll
        for (int k = 0; k < Tdim / 4; k++) {
            float4 v = trow[k];
            float2 lo = make_float2(exp2f(v.x * LOG2E), exp2f(v.y * LOG2E));
            float2 hi = make_float2(exp2f(v.z * LOG2E), exp2f(v.w * LOG2E));
            memcpy(&et[2 * k + 0], &lo, 8);
            memcpy(&et[2 * k + 1], &hi, 8);
        }
    }

    int job = blockIdx.x;
    while (job < NJOBS) {
        const int b1 = g_order[2 * job];
        const int b2 = g_order[2 * job + 1];
        const int len1 = lens[b1];
        const int len2 = lens[b2];
        const int l1m = len1 - 1, l2m = len2 - 1;
        const int lenmax = max(len1, len2);

        gs1[0][t] = (t == START_TAG) ? 1.0f : 0.0f;
        gs2[0][t] = (t == START_TAG) ? 1.0f : 0.0f;
        if (t == 0) { sh_w1[0] = 1.0f; sh_w2[0] = 1.0f; }
        float G1 = gs1[0][t], G2v = G1;
        float Ma1 = 0.0f, Ma2 = 0.0f;            // shift accumulators (log2)

        const float* emit1 = feats + (size_t)b1 * Ldim * Tdim + t;
        const float* emit2 = feats + (size_t)b2 * Ldim * Tdim + t;

        float ee1[PF], ee2[PF];
        #pragma unroll
        for (int k = 0; k < PF; k++) {
            ee1[k] = exp2f(emit1[min(k, l1m) * Tdim] * LOG2E);
            ee2[k] = exp2f(emit2[min(k, l2m) * Tdim] * LOG2E);
        }

        __syncthreads();

        const int len_pad = (lenmax + PF - 1) & ~(PF - 1);
        for (int i0 = 0; i0 < len_pad; i0 += PF) {
            #pragma unroll
            for (int j = 0; j < PF; j++) {
                const int i = i0 + j;
                const int p = i & 1;
                const bool act1 = (i < len1);      // block-uniform
                const bool act2 = (i < len2);

                float ec1 = ee1[j], ec2 = ee2[j];
                ee1[j] = exp2f(emit1[min(i + PF, l1m) * Tdim] * LOG2E);
                ee2[j] = exp2f(emit2[min(i + PF, l2m) * Tdim] * LOG2E);

                float w1 = sh_w1[p], w2 = sh_w2[p];
                float r1 = rcp_fast(w1), r2 = rcp_fast(w2);

                float s1 = matvec128(gs1[p], et);  // independent chains:
                float s2 = matvec128(gs2[p], et);  // ptxas interleaves

                if (act1) {
                    float u = s1 * ec1;
                    float G = u * r1;
                    gs1[p ^ 1][t] = G;
                    if (t == 0) sh_w1[p ^ 1] = u;
                    G1 = G;
                    Ma1 += __log2f(w1);
                }
                if (act2) {
                    float u = s2 * ec2;
                    float G = u * r2;
                    gs2[p ^ 1][t] = G;
                    if (t == 0) sh_w2[p ^ 1] = u;
                    G2v = G;
                    Ma2 += __log2f(w2);
                }
                __syncthreads();
            }
        }

        float fv1 = (__log2f(G1) + Ma1) * LN2;     // G==0 -> -inf, OK in LSE
        float fv2 = (__log2f(G2v) + Ma2) * LN2;

        float r1 = finish_batch(fv1, len1, b1, t, lane, warp,
                                feats, trans, tags, smax, ssum);
        float r2 = finish_batch(fv2, len2, b2, t, lane, warp,
                                feats, trans, tags, smax, ssum);
        if (t == 0) {
            g_partial[b1] = r1;
            g_partial[b2] = r2;
            sh_job = atomicAdd(&g_counter, 1);
        }
        __syncthreads();
        job = sh_job;
        __syncthreads();
    }

    // ---- fused final reduction: last CTA to finish computes the mean ----
    __threadfence();
    if (t == 0) sh_last = atomicAdd(&g_done, 1);
    __syncthreads();
    if (sh_last == NWORK - 1) {
        __threadfence();
        float v = 0.f;
        #pragma unroll
        for (int k = 0; k < Bdim / Tdim; k++)
            v += g_partial[k * Tdim + t];
        #pragma unroll
        for (int o = 16; o > 0; o >>= 1)
            v += __shfl_xor_sync(0xffffffffu, v, o);
        if (lane == 0) ssum[warp] = v;
        __syncthreads();
        if (t == 0)
            out[0] = ((ssum[0] + ssum[1]) + (ssum[2] + ssum[3])) * (1.0f / (float)Bdim);
    }
}

extern "C" void kernel_launch(void* const* d_in, const int* in_sizes, int n_in,
                              void* d_out, int out_size)
{
    const float* feats = (const float*)d_in[0];
    const float* trans = (const float*)d_in[1];
    const int*   tags  = (const int*)d_in[2];
    const int*   lens  = (const int*)d_in[3];
    float* out = (float*)d_out;

    crf_schedule_kernel<<<8, 64>>>(lens);
    crf_batch_kernel<<<NWORK, Tdim>>>(feats, trans, tags, lens, out);
}